// round 5
// baseline (speedup 1.0000x reference)
#include <cuda_runtime.h>
#include <cstdint>
#include <cstddef>

// ---------------- problem constants ----------------
#define BDIM 8
#define EDIM 512
#define LDIM 8192
#define KSZ  5
#define LC   8188      // LDIM - KSZ + 1
#define TD   4096      // LDIM / 2 (downsampled length)

typedef unsigned long long u64;

// ---------------- scratch (no allocations allowed) ----------------
__device__ float g_y[(size_t)BDIM * EDIM * LDIM];   // conv output (padded rows; t>=LC unwritten, always guarded)
__device__ float g_s[BDIM * LDIM];                  // score projection, zero for t>=LC
__device__ float g_att[BDIM * LDIM * 4];            // softmax weights per (b,t): [a1,a2,a3,unused]

// ---------------- f32x2 helpers (sm_100+ packed fp32) ----------------
__device__ __forceinline__ u64 dup2(float v) {
    u64 r;
    asm("mov.b64 %0, {%1, %1};" : "=l"(r) : "f"(v));
    return r;
}
__device__ __forceinline__ void fma2(u64& d, u64 a, u64 b) {
    asm("fma.rn.f32x2 %0, %1, %2, %0;" : "+l"(d) : "l"(a), "l"(b));
}
__device__ __forceinline__ float2 unp2(u64 v) {
    float2 f;
    asm("mov.b64 {%0, %1}, %2;" : "=f"(f.x), "=f"(f.y) : "l"(v));
    return f;
}

// ---------------- Kernel 1: valid conv1d as tiled GEMM ----------------
// y[b,e,t] = bias[e] + sum_{i,k} w[e,i,k] * x[b,i,t+k],  t in [0, LC)
// Tile: BE=128 e-rows x BT=128 t-cols per block, 256 threads, 8x8 per thread.
// Accumulators are f32x2 pairs along e; x values are dup-packed once per window.
#define BT 128
#define BE 128
#define BI 8

__global__ void __launch_bounds__(256, 2)
conv_kernel(const float* __restrict__ x,
            const float* __restrict__ w,
            const float* __restrict__ bias) {
    __shared__ __align__(16) float Xs[BI][136];        // BT + K-1 = 132 used, padded
    __shared__ __align__(16) float Ws[BI][KSZ][BE];

    const int b  = blockIdx.z;
    const int te = blockIdx.y * BE;
    const int tt = blockIdx.x * BT;
    const int tid = threadIdx.x;
    const int tx = tid & 15;        // t-group: 8 consecutive t
    const int ty = tid >> 4;        // e-group: 8 consecutive e (4 f32x2 pairs)

    u64 cc[4][8];
    #pragma unroll
    for (int p = 0; p < 4; p++)
        #pragma unroll
        for (int j = 0; j < 8; j++)
            cc[p][j] = 0ull;

    const float* xb = x + (size_t)b * EDIM * LDIM;

    for (int i0 = 0; i0 < EDIM; i0 += BI) {
        // ---- stage X tile: rows i0..i0+7, cols tt..tt+131 (guarded) ----
        #pragma unroll 2
        for (int idx = tid; idx < BI * 132; idx += 256) {
            int ii = idx / 132;
            int j  = idx - ii * 132;
            int gt = tt + j;
            Xs[ii][j] = (gt < LDIM) ? __ldg(&xb[(size_t)(i0 + ii) * LDIM + gt]) : 0.0f;
        }
        // ---- stage W tile: [ii][k][e] layout so e is contiguous ----
        #pragma unroll 2
        for (int idx = tid; idx < BE * BI * KSZ; idx += 256) {
            int e  = idx / (BI * KSZ);
            int r  = idx - e * (BI * KSZ);
            int ii = r / KSZ;
            int k  = r - ii * KSZ;
            Ws[ii][k][e] = __ldg(&w[((size_t)(te + e) * EDIM + (i0 + ii)) * KSZ + k]);
        }
        __syncthreads();

        #pragma unroll
        for (int ii = 0; ii < BI; ii++) {
            // 12-wide x window for this thread's 8 t's across all 5 taps
            const float4* xr = reinterpret_cast<const float4*>(&Xs[ii][tx * 8]);
            float4 q0 = xr[0], q1 = xr[1], q2 = xr[2];
            u64 wd[12];
            wd[0]  = dup2(q0.x); wd[1]  = dup2(q0.y); wd[2]  = dup2(q0.z); wd[3]  = dup2(q0.w);
            wd[4]  = dup2(q1.x); wd[5]  = dup2(q1.y); wd[6]  = dup2(q1.z); wd[7]  = dup2(q1.w);
            wd[8]  = dup2(q2.x); wd[9]  = dup2(q2.y); wd[10] = dup2(q2.z); wd[11] = dup2(q2.w);

            #pragma unroll
            for (int k = 0; k < KSZ; k++) {
                const u64* ap = reinterpret_cast<const u64*>(&Ws[ii][k][ty * 8]);
                u64 a0 = ap[0], a1 = ap[1], a2 = ap[2], a3 = ap[3];
                #pragma unroll
                for (int jt = 0; jt < 8; jt++) {
                    u64 bb = wd[k + jt];
                    fma2(cc[0][jt], a0, bb);
                    fma2(cc[1][jt], a1, bb);
                    fma2(cc[2][jt], a2, bb);
                    fma2(cc[3][jt], a3, bb);
                }
            }
        }
        __syncthreads();
    }

    // ---- epilogue: add bias, store rows (guard t < LC) ----
    const int tbase = tt + tx * 8;
    #pragma unroll
    for (int p = 0; p < 4; p++) {
        int e0 = te + ty * 8 + 2 * p;
        float b0 = bias[e0], b1 = bias[e0 + 1];
        float r0[8], r1[8];
        #pragma unroll
        for (int jt = 0; jt < 8; jt++) {
            float2 v = unp2(cc[p][jt]);
            r0[jt] = v.x + b0;
            r1[jt] = v.y + b1;
        }
        float* y0 = g_y + ((size_t)b * EDIM + e0) * LDIM + tbase;
        float* y1 = y0 + LDIM;
        if (tbase + 8 <= LC) {
            reinterpret_cast<float4*>(y0)[0] = make_float4(r0[0], r0[1], r0[2], r0[3]);
            reinterpret_cast<float4*>(y0)[1] = make_float4(r0[4], r0[5], r0[6], r0[7]);
            reinterpret_cast<float4*>(y1)[0] = make_float4(r1[0], r1[1], r1[2], r1[3]);
            reinterpret_cast<float4*>(y1)[1] = make_float4(r1[4], r1[5], r1[6], r1[7]);
        } else {
            #pragma unroll
            for (int jt = 0; jt < 8; jt++) {
                if (tbase + jt < LC) { y0[jt] = r0[jt]; y1[jt] = r1[jt]; }
            }
        }
    }
}

// ---------------- Kernel 2: score projection s[b,t] = sum_e y[b,e,t]*sw[e] ----------------
__global__ void score_kernel(const float* __restrict__ sw) {
    const int b = blockIdx.y;
    const int t = blockIdx.x * 256 + threadIdx.x;
    if (t >= LC) { g_s[b * LDIM + t] = 0.0f; return; }
    const float* y = g_y + (size_t)b * EDIM * LDIM + t;
    float acc = 0.0f;
    #pragma unroll 8
    for (int e = 0; e < EDIM; e++)
        acc += y[(size_t)e * LDIM] * __ldg(&sw[e]);
    g_s[b * LDIM + t] = acc;
}

// ---------------- Kernel 3: per-(b,t) softmax over widths {1,2,3} ----------------
// Padded regions contribute score 0 (and DO participate in the softmax),
// matching the reference's zero-padding of the repeated scores.
__global__ void att_kernel() {
    const int b = blockIdx.y;
    const int t = blockIdx.x * 256 + threadIdx.x;
    const float* s = g_s + b * LDIM;

    float sc1 = (t < LC) ? s[t] : 0.0f;
    int n2 = t >> 1;
    float sc2 = (t < LC) ? 0.5f * (s[2 * n2] + s[2 * n2 + 1]) : 0.0f;
    float sc3 = 0.0f;
    int m = t / 3;
    if (t < 8190) {
        // indices up to 3*2729+2 = 8189 < LDIM; g_s is zero for t >= LC
        sc3 = (s[3 * m] + s[3 * m + 1] + s[3 * m + 2]) * (1.0f / 3.0f);
    }
    float mx = fmaxf(sc1, fmaxf(sc2, sc3));
    float e1 = expf(sc1 - mx), e2 = expf(sc2 - mx), e3 = expf(sc3 - mx);
    float inv = 1.0f / (e1 + e2 + e3);
    float* a = g_att + ((size_t)b * LDIM + t) * 4;
    a[0] = e1 * inv;
    a[1] = e2 * inv;
    a[2] = e3 * inv;
}

// ---------------- Kernel 4: mix widths + downsample by 2 ----------------
__global__ void final_kernel(float* __restrict__ out) {
    const int b  = blockIdx.z;
    const int e  = blockIdx.y;
    const int td = blockIdx.x * 256 + threadIdx.x;   // 0..4095
    const float* y   = g_y   + ((size_t)b * EDIM + e) * LDIM;
    const float* att = g_att + (size_t)b * LDIM * 4;

    float z[2];
    #pragma unroll
    for (int h = 0; h < 2; h++) {
        int t = 2 * td + h;
        float a1 = att[t * 4 + 0];
        float a2 = att[t * 4 + 1];
        float a3 = att[t * 4 + 2];

        float v1 = (t < LC) ? y[t] : 0.0f;

        int n2 = t >> 1;   // t0 even, t1 odd share block n2 = td
        float v2 = (t < LC) ? 0.5f * (y[2 * n2] + y[2 * n2 + 1]) : 0.0f;

        float v3 = 0.0f;
        if (t < 8190) {
            int i0 = 3 * (t / 3);                 // <= 8187, always valid
            float s0 = y[i0];
            float s1 = (i0 + 1 < LC) ? y[i0 + 1] : 0.0f;
            float s2 = (i0 + 2 < LC) ? y[i0 + 2] : 0.0f;
            v3 = (s0 + s1 + s2) * (1.0f / 3.0f);
        }
        z[h] = v1 * a1 + v2 * a2 + v3 * a3;
    }
    out[((size_t)b * EDIM + e) * TD + td] = 0.5f * (z[0] + z[1]);
}

// ---------------- launch ----------------
extern "C" void kernel_launch(void* const* d_in, const int* in_sizes, int n_in,
                              void* d_out, int out_size) {
    (void)in_sizes; (void)n_in; (void)out_size;
    const float* x  = (const float*)d_in[0];   // [8,512,8192]
    const float* cw = (const float*)d_in[1];   // [512,512,5]
    const float* cb = (const float*)d_in[2];   // [512]
    const float* sw = (const float*)d_in[3];   // [512]
    float* out = (float*)d_out;                // [8,512,4096]

    dim3 cgrid(LDIM / BT, EDIM / BE, BDIM);    // 64 x 4 x 8 (last t-tile covers the LC tail)
    conv_kernel<<<cgrid, 256>>>(x, cw, cb);
    score_kernel<<<dim3(LDIM / 256, BDIM), 256>>>(sw);
    att_kernel<<<dim3(LDIM / 256, BDIM), 256>>>();
    final_kernel<<<dim3(TD / 256, EDIM, BDIM), 256>>>(out);
}

// round 11
// speedup vs baseline: 1.9573x; 1.9573x over previous
#include <cuda_runtime.h>
#include <cuda_bf16.h>
#include <cstdint>
#include <cstddef>

// ---------------- problem constants ----------------
#define BDIM 8
#define EDIM 512
#define LDIM 8192
#define KSZ  5
#define LC   8188      // LDIM - KSZ + 1
#define TD   4096      // LDIM / 2
#define KTOT 2560      // EDIM * KSZ
#define KC   32        // K elements per chunk
#define NCH  80        // KTOT / KC
#define MBLK 128
#define NBLK 128

// smem tile geometry: rows of KC bf16 padded to 40 elems (80 B) -> conflict-free ldmatrix
#define STRIDE_E 40
#define TILE_B   (128 * STRIDE_E * 2)    // 10240 B per tile
#define BUF_B    (4 * TILE_B)            // Ah | Al | Bh | Bl = 40960 B
#define SMEM_TOTAL (2 * BUF_B)           // double buffered = 81920 B

// ---------------- scratch (no allocations allowed) ----------------
__device__ float g_y[(size_t)BDIM * EDIM * LDIM];           // conv output
__device__ float g_s[BDIM * LDIM];                          // score projection
__device__ float g_att[BDIM * LDIM * 4];                    // softmax weights
__device__ __align__(16) __nv_bfloat16 g_wh[(size_t)EDIM * KTOT];  // W hi, [e][kappa]
__device__ __align__(16) __nv_bfloat16 g_wl[(size_t)EDIM * KTOT];  // W lo

// ---------------- PTX helpers (baseline ISA only: sm_80-safe) ----------------
__device__ __forceinline__ uint32_t smem_u32(const void* p) {
    uint32_t a;
    asm("{ .reg .u64 t; cvta.to.shared.u64 t, %1; cvt.u32.u64 %0, t; }" : "=r"(a) : "l"(p));
    return a;
}
__device__ __forceinline__ void ldsm_x4(uint32_t addr, uint32_t* r) {
    asm volatile("ldmatrix.sync.aligned.m8n8.x4.shared.b16 {%0,%1,%2,%3}, [%4];"
        : "=r"(r[0]), "=r"(r[1]), "=r"(r[2]), "=r"(r[3]) : "r"(addr));
}
__device__ __forceinline__ void mma_bf16(float* d, const uint32_t* a, const uint32_t* b) {
    asm volatile("mma.sync.aligned.m16n8k16.row.col.f32.bf16.bf16.f32 "
        "{%0,%1,%2,%3}, {%4,%5,%6,%7}, {%8,%9}, {%0,%1,%2,%3};"
        : "+f"(d[0]), "+f"(d[1]), "+f"(d[2]), "+f"(d[3])
        : "r"(a[0]), "r"(a[1]), "r"(a[2]), "r"(a[3]), "r"(b[0]), "r"(b[1]));
}
__device__ __forceinline__ uint32_t pack_bf16x2(unsigned short lo, unsigned short hi) {
    return (uint32_t)lo | ((uint32_t)hi << 16);
}

// ---------------- Kernel 0: split W into bf16 hi/lo ([e][kappa]), zero g_s ----------------
__global__ void prep_kernel(const float* __restrict__ w) {
    int idx = blockIdx.x * 256 + threadIdx.x;
    if (idx < EDIM * KTOT) {
        int e = idx / KTOT, kap = idx - e * KTOT;
        int i = kap / KSZ, k = kap - KSZ * i;
        float v = w[((size_t)e * EDIM + i) * KSZ + k];
        __nv_bfloat16 h = __float2bfloat16(v);
        g_wh[(size_t)e * KTOT + kap] = h;
        g_wl[(size_t)e * KTOT + kap] = __float2bfloat16(v - __bfloat162float(h));
    }
    if (idx < BDIM * LDIM) g_s[idx] = 0.0f;
}

// ---------------- Kernel 1: conv as bf16x3 warp-tiled mma.sync GEMM ----------------
// D[t,e] = sum_kappa A[t,kappa] * B[e,kappa];  A = im2col(x) split hi/lo on the fly,
// B = W hi/lo precomputed. Block 128t x 128e, 8 warps (4m x 2n), warp tile 32x64.
__global__ void __launch_bounds__(256, 1)
conv_mma_kernel(const float* __restrict__ x,
                const float* __restrict__ cb,
                const float* __restrict__ sw) {
    extern __shared__ char smem[];
    const uint32_t sb = smem_u32(smem);
    const int tid = threadIdx.x;
    const int wid = tid >> 5, lid = tid & 31;
    const int b  = blockIdx.z;
    const int te = blockIdx.y * NBLK;
    const int tt = blockIdx.x * MBLK;
    const float* xb = x + (size_t)b * EDIM * LDIM;

    const int t_r  = tid & 127;      // staging row (t for A, e for B)
    const int half = tid >> 7;       // which pair of 8-kappa groups

    float acc[2][8][4];
    #pragma unroll
    for (int i = 0; i < 2; i++)
        #pragma unroll
        for (int j = 0; j < 8; j++)
            #pragma unroll
            for (int q = 0; q < 4; q++)
                acc[i][j][q] = 0.0f;

    float pa[2][8];          // prefetched x values
    uint4 pbh[2], pbl[2];    // prefetched W hi/lo

    // ---- prologue: load + store chunk 0 ----
    #pragma unroll
    for (int it = 0; it < 2; it++) {
        const int j0 = (half * 2 + it) * 8;
        #pragma unroll
        for (int u = 0; u < 8; u++) {
            int kap = j0 + u;
            int i = kap / KSZ, k = kap - KSZ * i;
            int gt = tt + t_r + k;
            pa[it][u] = (gt < LDIM) ? __ldg(xb + (size_t)i * LDIM + gt) : 0.0f;
        }
        size_t src = (size_t)(te + t_r) * KTOT + j0;
        pbh[it] = __ldg(reinterpret_cast<const uint4*>(g_wh + src));
        pbl[it] = __ldg(reinterpret_cast<const uint4*>(g_wl + src));
    }
    {
        char* base = smem;   // buffer 0
        #pragma unroll
        for (int it = 0; it < 2; it++) {
            const int j0 = (half * 2 + it) * 8;
            unsigned short hs[8], ls[8];
            #pragma unroll
            for (int u = 0; u < 8; u++) {
                float v = pa[it][u];
                __nv_bfloat16 h = __float2bfloat16(v);
                hs[u] = __bfloat16_as_ushort(h);
                ls[u] = __bfloat16_as_ushort(__float2bfloat16(v - __bfloat162float(h)));
            }
            uint32_t off = (uint32_t)(t_r * (STRIDE_E * 2) + j0 * 2);
            *reinterpret_cast<uint4*>(base + off) =
                make_uint4(pack_bf16x2(hs[0], hs[1]), pack_bf16x2(hs[2], hs[3]),
                           pack_bf16x2(hs[4], hs[5]), pack_bf16x2(hs[6], hs[7]));
            *reinterpret_cast<uint4*>(base + TILE_B + off) =
                make_uint4(pack_bf16x2(ls[0], ls[1]), pack_bf16x2(ls[2], ls[3]),
                           pack_bf16x2(ls[4], ls[5]), pack_bf16x2(ls[6], ls[7]));
            *reinterpret_cast<uint4*>(base + 2 * TILE_B + off) = pbh[it];
            *reinterpret_cast<uint4*>(base + 3 * TILE_B + off) = pbl[it];
        }
    }
    __syncthreads();

    const int wm = (wid & 3) * 32;     // warp m offset
    const int wn = (wid >> 2) * 64;    // warp n offset
    // ldmatrix lane-address components (constant across chunks)
    const int a_row  = wm + (lid & 15);
    const int a_colk = (lid & 16) ? 8 : 0;
    const int b_q    = lid >> 3;
    const int b_row  = wn + ((b_q & 2) ? 8 : 0) + (lid & 7);
    const int b_colk = (b_q & 1) ? 8 : 0;

    for (int c = 0; c < NCH; c++) {
        const int d = c & 1;

        // ---- prefetch next chunk into registers (LDGs overlap MMAs below) ----
        if (c + 1 < NCH) {
            const int kap0 = (c + 1) * KC;
            #pragma unroll
            for (int it = 0; it < 2; it++) {
                const int j0 = (half * 2 + it) * 8;
                #pragma unroll
                for (int u = 0; u < 8; u++) {
                    int kap = kap0 + j0 + u;
                    int i = kap / KSZ, k = kap - KSZ * i;
                    int gt = tt + t_r + k;
                    pa[it][u] = (gt < LDIM) ? __ldg(xb + (size_t)i * LDIM + gt) : 0.0f;
                }
                size_t src = (size_t)(te + t_r) * KTOT + kap0 + j0;
                pbh[it] = __ldg(reinterpret_cast<const uint4*>(g_wh + src));
                pbl[it] = __ldg(reinterpret_cast<const uint4*>(g_wl + src));
            }
        }

        // ---- compute on buffer d ----
        {
            const uint32_t Ah = sb + d * BUF_B;
            const uint32_t Al = Ah + TILE_B;
            const uint32_t Bh = Ah + 2 * TILE_B;
            const uint32_t Bl = Ah + 3 * TILE_B;
            #pragma unroll
            for (int ks = 0; ks < 2; ks++) {
                const uint32_t acol = (uint32_t)((ks * 16 + a_colk) * 2);
                const uint32_t ao0 = (uint32_t)(a_row * (STRIDE_E * 2)) + acol;
                const uint32_t ao1 = ao0 + 16 * (STRIDE_E * 2);
                uint32_t ah0[4], ah1[4], al0[4], al1[4];
                ldsm_x4(Ah + ao0, ah0);
                ldsm_x4(Ah + ao1, ah1);
                ldsm_x4(Al + ao0, al0);
                ldsm_x4(Al + ao1, al1);
                const uint32_t bcol = (uint32_t)((ks * 16 + b_colk) * 2);
                #pragma unroll
                for (int ng = 0; ng < 4; ng++) {
                    const uint32_t bo = (uint32_t)((b_row + ng * 16) * (STRIDE_E * 2)) + bcol;
                    uint32_t bh[4], bl[4];
                    ldsm_x4(Bh + bo, bh);
                    ldsm_x4(Bl + bo, bl);
                    // pass 1: Ah x Bh
                    mma_bf16(acc[0][2 * ng],     ah0, &bh[0]);
                    mma_bf16(acc[0][2 * ng + 1], ah0, &bh[2]);
                    mma_bf16(acc[1][2 * ng],     ah1, &bh[0]);
                    mma_bf16(acc[1][2 * ng + 1], ah1, &bh[2]);
                    // pass 2: Ah x Bl
                    mma_bf16(acc[0][2 * ng],     ah0, &bl[0]);
                    mma_bf16(acc[0][2 * ng + 1], ah0, &bl[2]);
                    mma_bf16(acc[1][2 * ng],     ah1, &bl[0]);
                    mma_bf16(acc[1][2 * ng + 1], ah1, &bl[2]);
                    // pass 3: Al x Bh
                    mma_bf16(acc[0][2 * ng],     al0, &bh[0]);
                    mma_bf16(acc[0][2 * ng + 1], al0, &bh[2]);
                    mma_bf16(acc[1][2 * ng],     al1, &bh[0]);
                    mma_bf16(acc[1][2 * ng + 1], al1, &bh[2]);
                }
            }
        }

        // ---- store prefetched chunk into the other buffer ----
        if (c + 1 < NCH) {
            char* base = smem + (d ^ 1) * BUF_B;
            #pragma unroll
            for (int it = 0; it < 2; it++) {
                const int j0 = (half * 2 + it) * 8;
                unsigned short hs[8], ls[8];
                #pragma unroll
                for (int u = 0; u < 8; u++) {
                    float v = pa[it][u];
                    __nv_bfloat16 h = __float2bfloat16(v);
                    hs[u] = __bfloat16_as_ushort(h);
                    ls[u] = __bfloat16_as_ushort(__float2bfloat16(v - __bfloat162float(h)));
                }
                uint32_t off = (uint32_t)(t_r * (STRIDE_E * 2) + j0 * 2);
                *reinterpret_cast<uint4*>(base + off) =
                    make_uint4(pack_bf16x2(hs[0], hs[1]), pack_bf16x2(hs[2], hs[3]),
                               pack_bf16x2(hs[4], hs[5]), pack_bf16x2(hs[6], hs[7]));
                *reinterpret_cast<uint4*>(base + TILE_B + off) =
                    make_uint4(pack_bf16x2(ls[0], ls[1]), pack_bf16x2(ls[2], ls[3]),
                               pack_bf16x2(ls[4], ls[5]), pack_bf16x2(ls[6], ls[7]));
                *reinterpret_cast<uint4*>(base + 2 * TILE_B + off) = pbh[it];
                *reinterpret_cast<uint4*>(base + 3 * TILE_B + off) = pbl[it];
            }
        }
        __syncthreads();
    }

    // ---- epilogue: bias + store y + fused score projection ----
    // D fragment: c0:(t0,e0) c1:(t0,e0+1) c2:(t0+8,e0) c3:(t0+8,e0+1)
    const int r = lid & 3, qr = lid >> 2;
    #pragma unroll
    for (int mt = 0; mt < 2; mt++) {
        const int tg0 = tt + wm + mt * 16 + qr;   // and tg0 + 8
        float s0 = 0.0f, s1 = 0.0f;
        #pragma unroll
        for (int n8 = 0; n8 < 8; n8++) {
            const int e0 = te + wn + n8 * 8 + r * 2;
            const float cb0 = __ldg(&cb[e0]), cb1 = __ldg(&cb[e0 + 1]);
            const float sw0 = __ldg(&sw[e0]), sw1 = __ldg(&sw[e0 + 1]);
            float c0 = acc[mt][n8][0] + cb0;
            float c1 = acc[mt][n8][1] + cb1;
            float c2 = acc[mt][n8][2] + cb0;
            float c3 = acc[mt][n8][3] + cb1;
            float* y0 = g_y + ((size_t)b * EDIM + e0) * LDIM;
            float* y1 = y0 + LDIM;
            if (tg0 < LC)     { y0[tg0] = c0;     y1[tg0] = c1; }
            if (tg0 + 8 < LC) { y0[tg0 + 8] = c2; y1[tg0 + 8] = c3; }
            s0 += c0 * sw0 + c1 * sw1;
            s1 += c2 * sw0 + c3 * sw1;
        }
        // reduce over the 4 lanes of the quad (they share tg0)
        s0 += __shfl_xor_sync(0xFFFFFFFF, s0, 1);
        s0 += __shfl_xor_sync(0xFFFFFFFF, s0, 2);
        s1 += __shfl_xor_sync(0xFFFFFFFF, s1, 1);
        s1 += __shfl_xor_sync(0xFFFFFFFF, s1, 2);
        if (r == 0) {
            if (tg0 < LC)     atomicAdd(&g_s[b * LDIM + tg0], s0);
            if (tg0 + 8 < LC) atomicAdd(&g_s[b * LDIM + tg0 + 8], s1);
        }
    }
}

// ---------------- Kernel 2: per-(b,t) softmax over widths {1,2,3} ----------------
__global__ void att_kernel() {
    const int b = blockIdx.y;
    const int t = blockIdx.x * 256 + threadIdx.x;
    const float* s = g_s + b * LDIM;

    float sc1 = (t < LC) ? s[t] : 0.0f;
    int n2 = t >> 1;
    float sc2 = (t < LC) ? 0.5f * (s[2 * n2] + s[2 * n2 + 1]) : 0.0f;
    float sc3 = 0.0f;
    int m = t / 3;
    if (t < 8190) {
        sc3 = (s[3 * m] + s[3 * m + 1] + s[3 * m + 2]) * (1.0f / 3.0f);
    }
    float mx = fmaxf(sc1, fmaxf(sc2, sc3));
    float e1 = expf(sc1 - mx), e2 = expf(sc2 - mx), e3 = expf(sc3 - mx);
    float inv = 1.0f / (e1 + e2 + e3);
    float* a = g_att + ((size_t)b * LDIM + t) * 4;
    a[0] = e1 * inv;
    a[1] = e2 * inv;
    a[2] = e3 * inv;
    a[3] = 0.0f;
}

// ---------------- Kernel 3: mix widths + downsample by 2 ----------------
__global__ void final_kernel(float* __restrict__ out) {
    const int b  = blockIdx.z;
    const int e  = blockIdx.y;
    const int td = blockIdx.x * 256 + threadIdx.x;   // 0..4095
    const float* y   = g_y   + ((size_t)b * EDIM + e) * LDIM;
    const float* att = g_att + (size_t)b * LDIM * 4;

    float z[2];
    #pragma unroll
    for (int h = 0; h < 2; h++) {
        int t = 2 * td + h;
        float4 a4 = *reinterpret_cast<const float4*>(att + (size_t)t * 4);

        float v1 = (t < LC) ? y[t] : 0.0f;

        int n2 = t >> 1;
        float v2 = (t < LC) ? 0.5f * (y[2 * n2] + y[2 * n2 + 1]) : 0.0f;

        float v3 = 0.0f;
        if (t < 8190) {
            int i0 = 3 * (t / 3);
            float s0 = y[i0];
            float s1 = (i0 + 1 < LC) ? y[i0 + 1] : 0.0f;
            float s2 = (i0 + 2 < LC) ? y[i0 + 2] : 0.0f;
            v3 = (s0 + s1 + s2) * (1.0f / 3.0f);
        }
        z[h] = v1 * a4.x + v2 * a4.y + v3 * a4.z;
    }
    out[((size_t)b * EDIM + e) * TD + td] = 0.5f * (z[0] + z[1]);
}

// ---------------- launch ----------------
extern "C" void kernel_launch(void* const* d_in, const int* in_sizes, int n_in,
                              void* d_out, int out_size) {
    (void)in_sizes; (void)n_in; (void)out_size;
    const float* x  = (const float*)d_in[0];   // [8,512,8192]
    const float* cw = (const float*)d_in[1];   // [512,512,5]
    const float* cb = (const float*)d_in[2];   // [512]
    const float* sw = (const float*)d_in[3];   // [512]
    float* out = (float*)d_out;                // [8,512,4096]

    cudaFuncSetAttribute(conv_mma_kernel,
                         cudaFuncAttributeMaxDynamicSharedMemorySize, SMEM_TOTAL);

    prep_kernel<<<(EDIM * KTOT + 255) / 256, 256>>>(cw);
    conv_mma_kernel<<<dim3(LDIM / MBLK, EDIM / NBLK, BDIM), 256, SMEM_TOTAL>>>(x, cb, sw);
    att_kernel<<<dim3(LDIM / 256, BDIM), 256>>>();
    final_kernel<<<dim3(TD / 256, EDIM, BDIM), 256>>>(out);
}

// round 13
// speedup vs baseline: 2.9938x; 1.5295x over previous
#include <cuda_runtime.h>
#include <cuda_fp16.h>
#include <cstdint>
#include <cstddef>

// ---------------- problem constants ----------------
#define BDIM 8
#define EDIM 512
#define LDIM 8192
#define KSZ  5
#define LC   8188      // LDIM - KSZ + 1
#define TD   4096      // LDIM / 2
#define KTOT 2560      // EDIM * KSZ
#define KC   32        // K elements per chunk
#define NCH  80        // KTOT / KC
#define MBLK 128
#define NBLK 128

// smem tile geometry: rows of KC fp16 padded to 40 elems (80 B) -> conflict-free ldmatrix
#define STRIDE_E 40
#define TILE_B   (128 * STRIDE_E * 2)    // 10240 B per tile
#define BUF_B    (3 * TILE_B)            // A | Bh | Bl = 30720 B
#define SMEM_TOTAL (2 * BUF_B)           // double buffered = 61440 B

// ---------------- scratch (no allocations allowed) ----------------
__device__ float g_y[(size_t)BDIM * EDIM * LDIM];           // conv output
__device__ float g_s[BDIM * LDIM];                          // score projection
__device__ float g_att[BDIM * LDIM * 4];                    // softmax weights
__device__ __align__(16) __half g_wh[(size_t)EDIM * KTOT];  // W hi (fp16), [e][kappa]
__device__ __align__(16) __half g_wl[(size_t)EDIM * KTOT];  // W lo (fp16)

// ---------------- PTX helpers (baseline ISA only: sm_80-safe) ----------------
__device__ __forceinline__ uint32_t smem_u32(const void* p) {
    uint32_t a;
    asm("{ .reg .u64 t; cvta.to.shared.u64 t, %1; cvt.u32.u64 %0, t; }" : "=r"(a) : "l"(p));
    return a;
}
__device__ __forceinline__ void ldsm_x4(uint32_t addr, uint32_t* r) {
    asm volatile("ldmatrix.sync.aligned.m8n8.x4.shared.b16 {%0,%1,%2,%3}, [%4];"
        : "=r"(r[0]), "=r"(r[1]), "=r"(r[2]), "=r"(r[3]) : "r"(addr));
}
__device__ __forceinline__ void mma_fp16(float* d, const uint32_t* a, const uint32_t* b) {
    asm volatile("mma.sync.aligned.m16n8k16.row.col.f32.f16.f16.f32 "
        "{%0,%1,%2,%3}, {%4,%5,%6,%7}, {%8,%9}, {%0,%1,%2,%3};"
        : "+f"(d[0]), "+f"(d[1]), "+f"(d[2]), "+f"(d[3])
        : "r"(a[0]), "r"(a[1]), "r"(a[2]), "r"(a[3]), "r"(b[0]), "r"(b[1]));
}

// ---------------- Kernel 0: split W into fp16 hi/lo ([e][kappa]), zero g_s ----------------
__global__ void prep_kernel(const float* __restrict__ w) {
    int idx = blockIdx.x * 256 + threadIdx.x;
    if (idx < EDIM * KTOT) {
        int e = idx / KTOT, kap = idx - e * KTOT;
        int i = kap / KSZ, k = kap - KSZ * i;
        float v = w[((size_t)e * EDIM + i) * KSZ + k];
        __half h = __float2half_rn(v);
        g_wh[(size_t)e * KTOT + kap] = h;
        g_wl[(size_t)e * KTOT + kap] = __float2half_rn(v - __half2float(h));
    }
    if (idx < BDIM * LDIM) g_s[idx] = 0.0f;
}

// ---------------- Kernel 1: conv as fp16 2-pass warp-tiled mma.sync GEMM ----------------
// D[t,e] = sum_kappa A16[t,kappa] * (Bh + Bl)[e,kappa];  A = im2col(x) rounded to fp16,
// B = W split hi/lo (exact). Block 128t x 128e, 8 warps (4m x 2n), warp tile 32x64.
__global__ void __launch_bounds__(256, 2)
conv_mma_kernel(const float* __restrict__ x,
                const float* __restrict__ cb,
                const float* __restrict__ sw) {
    extern __shared__ char smem[];
    const uint32_t sb = smem_u32(smem);
    const int tid = threadIdx.x;
    const int wid = tid >> 5, lid = tid & 31;
    const int b  = blockIdx.z;
    const int te = blockIdx.y * NBLK;
    const int tt = blockIdx.x * MBLK;
    const float* xb = x + (size_t)b * EDIM * LDIM;

    const int t_r  = tid & 127;      // staging row (t for A, e for B)
    const int half = tid >> 7;       // which 16-kappa half of the chunk

    float acc[2][8][4];
    #pragma unroll
    for (int i = 0; i < 2; i++)
        #pragma unroll
        for (int j = 0; j < 8; j++)
            #pragma unroll
            for (int q = 0; q < 4; q++)
                acc[i][j][q] = 0.0f;

    uint32_t pa[2][4];       // prefetched x (packed fp16x2)
    uint4 pbh[2], pbl[2];    // prefetched W hi/lo

    // ---- prologue: load + store chunk 0 ----
    #pragma unroll
    for (int it = 0; it < 2; it++) {
        const int j0 = half * 16 + it * 8;
        #pragma unroll
        for (int uu = 0; uu < 4; uu++) {
            int kap0g = j0 + 2 * uu;
            int i0 = kap0g / KSZ,       k0 = kap0g - KSZ * i0;
            int i1 = (kap0g + 1) / KSZ, k1 = (kap0g + 1) - KSZ * i1;
            int gt0 = tt + t_r + k0, gt1 = tt + t_r + k1;
            float v0 = (gt0 < LDIM) ? __ldg(xb + (size_t)i0 * LDIM + gt0) : 0.0f;
            float v1 = (gt1 < LDIM) ? __ldg(xb + (size_t)i1 * LDIM + gt1) : 0.0f;
            __half2 hp = __floats2half2_rn(v0, v1);
            pa[it][uu] = *reinterpret_cast<uint32_t*>(&hp);
        }
        size_t src = (size_t)(te + t_r) * KTOT + j0;
        pbh[it] = __ldg(reinterpret_cast<const uint4*>(g_wh + src));
        pbl[it] = __ldg(reinterpret_cast<const uint4*>(g_wl + src));
    }
    {
        char* base = smem;   // buffer 0
        #pragma unroll
        for (int it = 0; it < 2; it++) {
            const int j0 = half * 16 + it * 8;
            uint32_t off = (uint32_t)(t_r * (STRIDE_E * 2) + j0 * 2);
            *reinterpret_cast<uint4*>(base + off) =
                make_uint4(pa[it][0], pa[it][1], pa[it][2], pa[it][3]);
            *reinterpret_cast<uint4*>(base + TILE_B + off)     = pbh[it];
            *reinterpret_cast<uint4*>(base + 2 * TILE_B + off) = pbl[it];
        }
    }
    __syncthreads();

    const int wm = (wid & 3) * 32;     // warp m offset
    const int wn = (wid >> 2) * 64;    // warp n offset
    // ldmatrix lane-address components (constant across chunks)
    const int a_row  = wm + (lid & 15);
    const int a_colk = (lid & 16) ? 8 : 0;
    const int b_q    = lid >> 3;
    const int b_row  = wn + ((b_q & 2) ? 8 : 0) + (lid & 7);
    const int b_colk = (b_q & 1) ? 8 : 0;

    for (int c = 0; c < NCH; c++) {
        const int d = c & 1;

        // ---- prefetch next chunk into registers (LDGs overlap MMAs below) ----
        if (c + 1 < NCH) {
            const int kap0 = (c + 1) * KC;
            #pragma unroll
            for (int it = 0; it < 2; it++) {
                const int j0 = half * 16 + it * 8;
                #pragma unroll
                for (int uu = 0; uu < 4; uu++) {
                    int kg = kap0 + j0 + 2 * uu;
                    int i0 = kg / KSZ,       k0 = kg - KSZ * i0;
                    int i1 = (kg + 1) / KSZ, k1 = (kg + 1) - KSZ * i1;
                    int gt0 = tt + t_r + k0, gt1 = tt + t_r + k1;
                    float v0 = (gt0 < LDIM) ? __ldg(xb + (size_t)i0 * LDIM + gt0) : 0.0f;
                    float v1 = (gt1 < LDIM) ? __ldg(xb + (size_t)i1 * LDIM + gt1) : 0.0f;
                    __half2 hp = __floats2half2_rn(v0, v1);
                    pa[it][uu] = *reinterpret_cast<uint32_t*>(&hp);
                }
                size_t src = (size_t)(te + t_r) * KTOT + kap0 + j0;
                pbh[it] = __ldg(reinterpret_cast<const uint4*>(g_wh + src));
                pbl[it] = __ldg(reinterpret_cast<const uint4*>(g_wl + src));
            }
        }

        // ---- compute on buffer d ----
        {
            const uint32_t At = sb + d * BUF_B;
            const uint32_t Bh = At + TILE_B;
            const uint32_t Bl = At + 2 * TILE_B;
            #pragma unroll
            for (int ks = 0; ks < 2; ks++) {
                const uint32_t acol = (uint32_t)((ks * 16 + a_colk) * 2);
                const uint32_t ao0 = (uint32_t)(a_row * (STRIDE_E * 2)) + acol;
                const uint32_t ao1 = ao0 + 16 * (STRIDE_E * 2);
                uint32_t a0[4], a1[4];
                ldsm_x4(At + ao0, a0);
                ldsm_x4(At + ao1, a1);
                const uint32_t bcol = (uint32_t)((ks * 16 + b_colk) * 2);
                #pragma unroll
                for (int ng = 0; ng < 4; ng++) {
                    const uint32_t bo = (uint32_t)((b_row + ng * 16) * (STRIDE_E * 2)) + bcol;
                    uint32_t bh[4], bl[4];
                    ldsm_x4(Bh + bo, bh);
                    ldsm_x4(Bl + bo, bl);
                    // pass 1: A x Bh
                    mma_fp16(acc[0][2 * ng],     a0, &bh[0]);
                    mma_fp16(acc[0][2 * ng + 1], a0, &bh[2]);
                    mma_fp16(acc[1][2 * ng],     a1, &bh[0]);
                    mma_fp16(acc[1][2 * ng + 1], a1, &bh[2]);
                    // pass 2: A x Bl
                    mma_fp16(acc[0][2 * ng],     a0, &bl[0]);
                    mma_fp16(acc[0][2 * ng + 1], a0, &bl[2]);
                    mma_fp16(acc[1][2 * ng],     a1, &bl[0]);
                    mma_fp16(acc[1][2 * ng + 1], a1, &bl[2]);
                }
            }
        }

        // ---- store prefetched chunk into the other buffer ----
        if (c + 1 < NCH) {
            char* base = smem + (d ^ 1) * BUF_B;
            #pragma unroll
            for (int it = 0; it < 2; it++) {
                const int j0 = half * 16 + it * 8;
                uint32_t off = (uint32_t)(t_r * (STRIDE_E * 2) + j0 * 2);
                *reinterpret_cast<uint4*>(base + off) =
                    make_uint4(pa[it][0], pa[it][1], pa[it][2], pa[it][3]);
                *reinterpret_cast<uint4*>(base + TILE_B + off)     = pbh[it];
                *reinterpret_cast<uint4*>(base + 2 * TILE_B + off) = pbl[it];
            }
        }
        __syncthreads();
    }

    // ---- epilogue: bias + store y + fused score projection ----
    // D fragment: c0:(t0,e0) c1:(t0,e0+1) c2:(t0+8,e0) c3:(t0+8,e0+1)
    const int r = lid & 3, qr = lid >> 2;
    #pragma unroll
    for (int mt = 0; mt < 2; mt++) {
        const int tg0 = tt + wm + mt * 16 + qr;   // and tg0 + 8
        float s0 = 0.0f, s1 = 0.0f;
        #pragma unroll
        for (int n8 = 0; n8 < 8; n8++) {
            const int e0 = te + wn + n8 * 8 + r * 2;
            const float cb0 = __ldg(&cb[e0]), cb1 = __ldg(&cb[e0 + 1]);
            const float sw0 = __ldg(&sw[e0]), sw1 = __ldg(&sw[e0 + 1]);
            float c0 = acc[mt][n8][0] + cb0;
            float c1 = acc[mt][n8][1] + cb1;
            float c2 = acc[mt][n8][2] + cb0;
            float c3 = acc[mt][n8][3] + cb1;
            float* y0 = g_y + ((size_t)b * EDIM + e0) * LDIM;
            float* y1 = y0 + LDIM;
            if (tg0 < LC)     { y0[tg0] = c0;     y1[tg0] = c1; }
            if (tg0 + 8 < LC) { y0[tg0 + 8] = c2; y1[tg0 + 8] = c3; }
            s0 += c0 * sw0 + c1 * sw1;
            s1 += c2 * sw0 + c3 * sw1;
        }
        // reduce over the 4 lanes of the quad (they share tg0)
        s0 += __shfl_xor_sync(0xFFFFFFFF, s0, 1);
        s0 += __shfl_xor_sync(0xFFFFFFFF, s0, 2);
        s1 += __shfl_xor_sync(0xFFFFFFFF, s1, 1);
        s1 += __shfl_xor_sync(0xFFFFFFFF, s1, 2);
        if (r == 0) {
            if (tg0 < LC)     atomicAdd(&g_s[b * LDIM + tg0], s0);
            if (tg0 + 8 < LC) atomicAdd(&g_s[b * LDIM + tg0 + 8], s1);
        }
    }
}

// ---------------- Kernel 2: per-(b,t) softmax over widths {1,2,3} ----------------
__global__ void att_kernel() {
    const int b = blockIdx.y;
    const int t = blockIdx.x * 256 + threadIdx.x;
    const float* s = g_s + b * LDIM;

    float sc1 = (t < LC) ? s[t] : 0.0f;
    int n2 = t >> 1;
    float sc2 = (t < LC) ? 0.5f * (s[2 * n2] + s[2 * n2 + 1]) : 0.0f;
    float sc3 = 0.0f;
    int m = t / 3;
    if (t < 8190) {
        sc3 = (s[3 * m] + s[3 * m + 1] + s[3 * m + 2]) * (1.0f / 3.0f);
    }
    float mx = fmaxf(sc1, fmaxf(sc2, sc3));
    float e1 = expf(sc1 - mx), e2 = expf(sc2 - mx), e3 = expf(sc3 - mx);
    float inv = 1.0f / (e1 + e2 + e3);
    float* a = g_att + ((size_t)b * LDIM + t) * 4;
    a[0] = e1 * inv;
    a[1] = e2 * inv;
    a[2] = e3 * inv;
    a[3] = 0.0f;
}

// ---------------- Kernel 3: mix widths + downsample by 2 ----------------
__global__ void final_kernel(float* __restrict__ out) {
    const int b  = blockIdx.z;
    const int e  = blockIdx.y;
    const int td = blockIdx.x * 256 + threadIdx.x;   // 0..4095
    const float* y   = g_y   + ((size_t)b * EDIM + e) * LDIM;
    const float* att = g_att + (size_t)b * LDIM * 4;

    float z[2];
    #pragma unroll
    for (int h = 0; h < 2; h++) {
        int t = 2 * td + h;
        float4 a4 = *reinterpret_cast<const float4*>(att + (size_t)t * 4);

        float v1 = (t < LC) ? y[t] : 0.0f;

        int n2 = t >> 1;
        float v2 = (t < LC) ? 0.5f * (y[2 * n2] + y[2 * n2 + 1]) : 0.0f;

        float v3 = 0.0f;
        if (t < 8190) {
            int i0 = 3 * (t / 3);
            float s0 = y[i0];
            float s1 = (i0 + 1 < LC) ? y[i0 + 1] : 0.0f;
            float s2 = (i0 + 2 < LC) ? y[i0 + 2] : 0.0f;
            v3 = (s0 + s1 + s2) * (1.0f / 3.0f);
        }
        z[h] = v1 * a4.x + v2 * a4.y + v3 * a4.z;
    }
    out[((size_t)b * EDIM + e) * TD + td] = 0.5f * (z[0] + z[1]);
}

// ---------------- launch ----------------
extern "C" void kernel_launch(void* const* d_in, const int* in_sizes, int n_in,
                              void* d_out, int out_size) {
    (void)in_sizes; (void)n_in; (void)out_size;
    const float* x  = (const float*)d_in[0];   // [8,512,8192]
    const float* cw = (const float*)d_in[1];   // [512,512,5]
    const float* cb = (const float*)d_in[2];   // [512]
    const float* sw = (const float*)d_in[3];   // [512]
    float* out = (float*)d_out;                // [8,512,4096]

    cudaFuncSetAttribute(conv_mma_kernel,
                         cudaFuncAttributeMaxDynamicSharedMemorySize, SMEM_TOTAL);

    prep_kernel<<<(EDIM * KTOT + 255) / 256, 256>>>(cw);
    conv_mma_kernel<<<dim3(LDIM / MBLK, EDIM / NBLK, BDIM), 256, SMEM_TOTAL>>>(x, cb, sw);
    att_kernel<<<dim3(LDIM / 256, BDIM), 256>>>();
    final_kernel<<<dim3(TD / 256, EDIM, BDIM), 256>>>(out);
}

// round 14
// speedup vs baseline: 4.5346x; 1.5146x over previous
#include <cuda_runtime.h>
#include <cuda_fp16.h>
#include <cstdint>
#include <cstddef>

// ---------------- problem constants ----------------
#define BDIM 8
#define EDIM 512
#define LDIM 8192
#define KSZ  5
#define LC   8188      // LDIM - KSZ + 1
#define TD   4096      // LDIM / 2
#define KTOT 2560      // EDIM * KSZ
#define KC   32        // K elements per chunk
#define NCH  80        // KTOT / KC
#define MBLK 128
#define NBLK 128

// smem tile geometry: rows of KC fp16 padded to 40 elems (80 B) -> conflict-free ldmatrix
#define STRIDE_E 40
#define TILE_B   (128 * STRIDE_E * 2)    // 10240 B per tile
#define BUF_B    (2 * TILE_B)            // A | B = 20480 B
#define SMEM_TOTAL (2 * BUF_B)           // double buffered = 40960 B

// ---------------- scratch (no allocations allowed) ----------------
__device__ float g_y[(size_t)BDIM * EDIM * LDIM];           // conv output
__device__ float g_s[BDIM * LDIM];                          // score projection
__device__ float g_att[BDIM * LDIM * 4];                    // softmax weights
__device__ __align__(16) __half g_wf[(size_t)EDIM * KTOT];  // W (fp16), [e][kappa]

// ---------------- PTX helpers (baseline ISA only: sm_80-safe) ----------------
__device__ __forceinline__ uint32_t smem_u32(const void* p) {
    uint32_t a;
    asm("{ .reg .u64 t; cvta.to.shared.u64 t, %1; cvt.u32.u64 %0, t; }" : "=r"(a) : "l"(p));
    return a;
}
__device__ __forceinline__ void ldsm_x4(uint32_t addr, uint32_t* r) {
    asm volatile("ldmatrix.sync.aligned.m8n8.x4.shared.b16 {%0,%1,%2,%3}, [%4];"
        : "=r"(r[0]), "=r"(r[1]), "=r"(r[2]), "=r"(r[3]) : "r"(addr));
}
__device__ __forceinline__ void mma_fp16(float* d, const uint32_t* a, const uint32_t* b) {
    asm volatile("mma.sync.aligned.m16n8k16.row.col.f32.f16.f16.f32 "
        "{%0,%1,%2,%3}, {%4,%5,%6,%7}, {%8,%9}, {%0,%1,%2,%3};"
        : "+f"(d[0]), "+f"(d[1]), "+f"(d[2]), "+f"(d[3])
        : "r"(a[0]), "r"(a[1]), "r"(a[2]), "r"(a[3]), "r"(b[0]), "r"(b[1]));
}

// ---------------- Kernel 0: round W to fp16 ([e][kappa]), zero g_s ----------------
__global__ void prep_kernel(const float* __restrict__ w) {
    int idx = blockIdx.x * 256 + threadIdx.x;
    if (idx < EDIM * KTOT) {
        int e = idx / KTOT, kap = idx - e * KTOT;
        int i = kap / KSZ, k = kap - KSZ * i;
        float v = w[((size_t)e * EDIM + i) * KSZ + k];
        g_wf[(size_t)e * KTOT + kap] = __float2half_rn(v);
    }
    if (idx < BDIM * LDIM) g_s[idx] = 0.0f;
}

// ---------------- Kernel 1: conv as single-pass fp16 warp-tiled mma.sync GEMM ----------------
// D[t,e] = sum_kappa A16[t,kappa] * B16[e,kappa];  A = im2col(x) rounded to fp16,
// B = W rounded to fp16. Block 128t x 128e, 8 warps (4m x 2n), warp tile 32x64.
__global__ void __launch_bounds__(256, 2)
conv_mma_kernel(const float* __restrict__ x,
                const float* __restrict__ cb,
                const float* __restrict__ sw) {
    extern __shared__ char smem[];
    const uint32_t sb = smem_u32(smem);
    const int tid = threadIdx.x;
    const int wid = tid >> 5, lid = tid & 31;
    const int b  = blockIdx.z;
    const int te = blockIdx.y * NBLK;
    const int tt = blockIdx.x * MBLK;
    const float* xb = x + (size_t)b * EDIM * LDIM;

    const int t_r  = tid & 127;      // staging row (t for A, e for B)
    const int half = tid >> 7;       // which 16-kappa half of the chunk

    float acc[2][8][4];
    #pragma unroll
    for (int i = 0; i < 2; i++)
        #pragma unroll
        for (int j = 0; j < 8; j++)
            #pragma unroll
            for (int q = 0; q < 4; q++)
                acc[i][j][q] = 0.0f;

    uint32_t pa[2][4];       // prefetched x (packed fp16x2)
    uint4 pb[2];             // prefetched W

    // ---- prologue: load + store chunk 0 ----
    #pragma unroll
    for (int it = 0; it < 2; it++) {
        const int j0 = half * 16 + it * 8;
        #pragma unroll
        for (int uu = 0; uu < 4; uu++) {
            int kap0g = j0 + 2 * uu;
            int i0 = kap0g / KSZ,       k0 = kap0g - KSZ * i0;
            int i1 = (kap0g + 1) / KSZ, k1 = (kap0g + 1) - KSZ * i1;
            int gt0 = tt + t_r + k0, gt1 = tt + t_r + k1;
            float v0 = (gt0 < LDIM) ? __ldg(xb + (size_t)i0 * LDIM + gt0) : 0.0f;
            float v1 = (gt1 < LDIM) ? __ldg(xb + (size_t)i1 * LDIM + gt1) : 0.0f;
            __half2 hp = __floats2half2_rn(v0, v1);
            pa[it][uu] = *reinterpret_cast<uint32_t*>(&hp);
        }
        size_t src = (size_t)(te + t_r) * KTOT + j0;
        pb[it] = __ldg(reinterpret_cast<const uint4*>(g_wf + src));
    }
    {
        char* base = smem;   // buffer 0
        #pragma unroll
        for (int it = 0; it < 2; it++) {
            const int j0 = half * 16 + it * 8;
            uint32_t off = (uint32_t)(t_r * (STRIDE_E * 2) + j0 * 2);
            *reinterpret_cast<uint4*>(base + off) =
                make_uint4(pa[it][0], pa[it][1], pa[it][2], pa[it][3]);
            *reinterpret_cast<uint4*>(base + TILE_B + off) = pb[it];
        }
    }
    __syncthreads();

    const int wm = (wid & 3) * 32;     // warp m offset
    const int wn = (wid >> 2) * 64;    // warp n offset
    // ldmatrix lane-address components (constant across chunks)
    const int a_row  = wm + (lid & 15);
    const int a_colk = (lid & 16) ? 8 : 0;
    const int b_q    = lid >> 3;
    const int b_row  = wn + ((b_q & 2) ? 8 : 0) + (lid & 7);
    const int b_colk = (b_q & 1) ? 8 : 0;

    for (int c = 0; c < NCH; c++) {
        const int d = c & 1;

        // ---- prefetch next chunk into registers (LDGs overlap MMAs below) ----
        if (c + 1 < NCH) {
            const int kap0 = (c + 1) * KC;
            #pragma unroll
            for (int it = 0; it < 2; it++) {
                const int j0 = half * 16 + it * 8;
                #pragma unroll
                for (int uu = 0; uu < 4; uu++) {
                    int kg = kap0 + j0 + 2 * uu;
                    int i0 = kg / KSZ,       k0 = kg - KSZ * i0;
                    int i1 = (kg + 1) / KSZ, k1 = (kg + 1) - KSZ * i1;
                    int gt0 = tt + t_r + k0, gt1 = tt + t_r + k1;
                    float v0 = (gt0 < LDIM) ? __ldg(xb + (size_t)i0 * LDIM + gt0) : 0.0f;
                    float v1 = (gt1 < LDIM) ? __ldg(xb + (size_t)i1 * LDIM + gt1) : 0.0f;
                    __half2 hp = __floats2half2_rn(v0, v1);
                    pa[it][uu] = *reinterpret_cast<uint32_t*>(&hp);
                }
                size_t src = (size_t)(te + t_r) * KTOT + kap0 + j0;
                pb[it] = __ldg(reinterpret_cast<const uint4*>(g_wf + src));
            }
        }

        // ---- compute on buffer d ----
        {
            const uint32_t At = sb + d * BUF_B;
            const uint32_t Bt = At + TILE_B;
            #pragma unroll
            for (int ks = 0; ks < 2; ks++) {
                const uint32_t acol = (uint32_t)((ks * 16 + a_colk) * 2);
                const uint32_t ao0 = (uint32_t)(a_row * (STRIDE_E * 2)) + acol;
                const uint32_t ao1 = ao0 + 16 * (STRIDE_E * 2);
                uint32_t a0[4], a1[4];
                ldsm_x4(At + ao0, a0);
                ldsm_x4(At + ao1, a1);
                const uint32_t bcol = (uint32_t)((ks * 16 + b_colk) * 2);
                #pragma unroll
                for (int ng = 0; ng < 4; ng++) {
                    const uint32_t bo = (uint32_t)((b_row + ng * 16) * (STRIDE_E * 2)) + bcol;
                    uint32_t bb[4];
                    ldsm_x4(Bt + bo, bb);
                    mma_fp16(acc[0][2 * ng],     a0, &bb[0]);
                    mma_fp16(acc[0][2 * ng + 1], a0, &bb[2]);
                    mma_fp16(acc[1][2 * ng],     a1, &bb[0]);
                    mma_fp16(acc[1][2 * ng + 1], a1, &bb[2]);
                }
            }
        }

        // ---- store prefetched chunk into the other buffer ----
        if (c + 1 < NCH) {
            char* base = smem + (d ^ 1) * BUF_B;
            #pragma unroll
            for (int it = 0; it < 2; it++) {
                const int j0 = half * 16 + it * 8;
                uint32_t off = (uint32_t)(t_r * (STRIDE_E * 2) + j0 * 2);
                *reinterpret_cast<uint4*>(base + off) =
                    make_uint4(pa[it][0], pa[it][1], pa[it][2], pa[it][3]);
                *reinterpret_cast<uint4*>(base + TILE_B + off) = pb[it];
            }
        }
        __syncthreads();
    }

    // ---- epilogue: bias + store y + fused score projection ----
    // D fragment: c0:(t0,e0) c1:(t0,e0+1) c2:(t0+8,e0) c3:(t0+8,e0+1)
    const int r = lid & 3, qr = lid >> 2;
    #pragma unroll
    for (int mt = 0; mt < 2; mt++) {
        const int tg0 = tt + wm + mt * 16 + qr;   // and tg0 + 8
        float s0 = 0.0f, s1 = 0.0f;
        #pragma unroll
        for (int n8 = 0; n8 < 8; n8++) {
            const int e0 = te + wn + n8 * 8 + r * 2;
            const float cb0 = __ldg(&cb[e0]), cb1 = __ldg(&cb[e0 + 1]);
            const float sw0 = __ldg(&sw[e0]), sw1 = __ldg(&sw[e0 + 1]);
            float c0 = acc[mt][n8][0] + cb0;
            float c1 = acc[mt][n8][1] + cb1;
            float c2 = acc[mt][n8][2] + cb0;
            float c3 = acc[mt][n8][3] + cb1;
            float* y0 = g_y + ((size_t)b * EDIM + e0) * LDIM;
            float* y1 = y0 + LDIM;
            if (tg0 < LC)     { y0[tg0] = c0;     y1[tg0] = c1; }
            if (tg0 + 8 < LC) { y0[tg0 + 8] = c2; y1[tg0 + 8] = c3; }
            s0 += c0 * sw0 + c1 * sw1;
            s1 += c2 * sw0 + c3 * sw1;
        }
        // reduce over the 4 lanes of the quad (they share tg0)
        s0 += __shfl_xor_sync(0xFFFFFFFF, s0, 1);
        s0 += __shfl_xor_sync(0xFFFFFFFF, s0, 2);
        s1 += __shfl_xor_sync(0xFFFFFFFF, s1, 1);
        s1 += __shfl_xor_sync(0xFFFFFFFF, s1, 2);
        if (r == 0) {
            if (tg0 < LC)     atomicAdd(&g_s[b * LDIM + tg0], s0);
            if (tg0 + 8 < LC) atomicAdd(&g_s[b * LDIM + tg0 + 8], s1);
        }
    }
}

// ---------------- Kernel 2: per-(b,t) softmax over widths {1,2,3} ----------------
__global__ void att_kernel() {
    const int b = blockIdx.y;
    const int t = blockIdx.x * 256 + threadIdx.x;
    const float* s = g_s + b * LDIM;

    float sc1 = (t < LC) ? s[t] : 0.0f;
    int n2 = t >> 1;
    float sc2 = (t < LC) ? 0.5f * (s[2 * n2] + s[2 * n2 + 1]) : 0.0f;
    float sc3 = 0.0f;
    int m = t / 3;
    if (t < 8190) {
        sc3 = (s[3 * m] + s[3 * m + 1] + s[3 * m + 2]) * (1.0f / 3.0f);
    }
    float mx = fmaxf(sc1, fmaxf(sc2, sc3));
    float e1 = expf(sc1 - mx), e2 = expf(sc2 - mx), e3 = expf(sc3 - mx);
    float inv = 1.0f / (e1 + e2 + e3);
    float* a = g_att + ((size_t)b * LDIM + t) * 4;
    a[0] = e1 * inv;
    a[1] = e2 * inv;
    a[2] = e3 * inv;
    a[3] = 0.0f;
}

// ---------------- Kernel 3: mix widths + downsample by 2 ----------------
__global__ void final_kernel(float* __restrict__ out) {
    const int b  = blockIdx.z;
    const int e  = blockIdx.y;
    const int td = blockIdx.x * 256 + threadIdx.x;   // 0..4095
    const float* y   = g_y   + ((size_t)b * EDIM + e) * LDIM;
    const float* att = g_att + (size_t)b * LDIM * 4;

    float z[2];
    #pragma unroll
    for (int h = 0; h < 2; h++) {
        int t = 2 * td + h;
        float4 a4 = *reinterpret_cast<const float4*>(att + (size_t)t * 4);

        float v1 = (t < LC) ? y[t] : 0.0f;

        int n2 = t >> 1;
        float v2 = (t < LC) ? 0.5f * (y[2 * n2] + y[2 * n2 + 1]) : 0.0f;

        float v3 = 0.0f;
        if (t < 8190) {
            int i0 = 3 * (t / 3);
            float s0 = y[i0];
            float s1 = (i0 + 1 < LC) ? y[i0 + 1] : 0.0f;
            float s2 = (i0 + 2 < LC) ? y[i0 + 2] : 0.0f;
            v3 = (s0 + s1 + s2) * (1.0f / 3.0f);
        }
        z[h] = v1 * a4.x + v2 * a4.y + v3 * a4.z;
    }
    out[((size_t)b * EDIM + e) * TD + td] = 0.5f * (z[0] + z[1]);
}

// ---------------- launch ----------------
extern "C" void kernel_launch(void* const* d_in, const int* in_sizes, int n_in,
                              void* d_out, int out_size) {
    (void)in_sizes; (void)n_in; (void)out_size;
    const float* x  = (const float*)d_in[0];   // [8,512,8192]
    const float* cw = (const float*)d_in[1];   // [512,512,5]
    const float* cb = (const float*)d_in[2];   // [512]
    const float* sw = (const float*)d_in[3];   // [512]
    float* out = (float*)d_out;                // [8,512,4096]

    cudaFuncSetAttribute(conv_mma_kernel,
                         cudaFuncAttributeMaxDynamicSharedMemorySize, SMEM_TOTAL);

    prep_kernel<<<(EDIM * KTOT + 255) / 256, 256>>>(cw);
    conv_mma_kernel<<<dim3(LDIM / MBLK, EDIM / NBLK, BDIM), 256, SMEM_TOTAL>>>(x, cb, sw);
    att_kernel<<<dim3(LDIM / 256, BDIM), 256>>>();
    final_kernel<<<dim3(TD / 256, EDIM, BDIM), 256>>>(out);
}

// round 15
// speedup vs baseline: 5.0028x; 1.1033x over previous
#include <cuda_runtime.h>
#include <cuda_fp16.h>
#include <cstdint>
#include <cstddef>

// ---------------- problem constants ----------------
#define BDIM 8
#define EDIM 512
#define LDIM 8192
#define KSZ  5
#define LC   8188      // LDIM - KSZ + 1
#define TD   4096      // LDIM / 2
#define MBLK 128       // t tile
#define NBLK 256       // e tile
#define IBLK 16        // i (in-channel) per chunk
#define NCHI 32        // EDIM / IBLK

// smem geometry
#define A_STRIDE_B 272                 // 128 halves (256B) + 16B pad -> conflict-free trans ldmatrix
#define A_TILE     (IBLK * A_STRIDE_B) // 4352 B
#define A_SZ       (KSZ * A_TILE)      // 21760 B
#define B_STRIDE_B 32                  // 16 halves per row (2-way ldsm conflict: negligible)
#define B_TILE     (NBLK * B_STRIDE_B) // 8192 B
#define B_SZ       (KSZ * B_TILE)      // 40960 B
#define BUF_B      (A_SZ + B_SZ)       // 62720 B
#define SMEM_TOTAL (2 * BUF_B)         // 125440 B

// ---------------- scratch (no allocations allowed) ----------------
__device__ float g_y[(size_t)BDIM * EDIM * LDIM];           // conv output
__device__ float g_s[BDIM * LDIM];                          // score projection
__device__ float g_att[BDIM * LDIM * 4];                    // softmax weights
// 5 pre-shifted fp16 copies of x: g_xh5[k][b][i][t] = fp16(x[b][i][t+k]) (0 if OOB)
__device__ __align__(16) __half g_xh5[(size_t)KSZ * BDIM * EDIM * LDIM];
// fp16 weights: g_wk5[k][e][i] = fp16(W[e][i][k])
__device__ __align__(16) __half g_wk5[(size_t)KSZ * EDIM * EDIM];

// ---------------- PTX helpers (baseline ISA: sm_80-safe, compiles at compute_103) ----------------
__device__ __forceinline__ uint32_t smem_u32(const void* p) {
    uint32_t a;
    asm("{ .reg .u64 t; cvta.to.shared.u64 t, %1; cvt.u32.u64 %0, t; }" : "=r"(a) : "l"(p));
    return a;
}
__device__ __forceinline__ void ldsm_x4(uint32_t addr, uint32_t* r) {
    asm volatile("ldmatrix.sync.aligned.m8n8.x4.shared.b16 {%0,%1,%2,%3}, [%4];"
        : "=r"(r[0]), "=r"(r[1]), "=r"(r[2]), "=r"(r[3]) : "r"(addr));
}
__device__ __forceinline__ void ldsm_x4_t(uint32_t addr, uint32_t* r) {
    asm volatile("ldmatrix.sync.aligned.m8n8.x4.trans.shared.b16 {%0,%1,%2,%3}, [%4];"
        : "=r"(r[0]), "=r"(r[1]), "=r"(r[2]), "=r"(r[3]) : "r"(addr));
}
__device__ __forceinline__ void mma_fp16(float* d, const uint32_t* a, const uint32_t* b) {
    asm volatile("mma.sync.aligned.m16n8k16.row.col.f32.f16.f16.f32 "
        "{%0,%1,%2,%3}, {%4,%5,%6,%7}, {%8,%9}, {%0,%1,%2,%3};"
        : "+f"(d[0]), "+f"(d[1]), "+f"(d[2]), "+f"(d[3])
        : "r"(a[0]), "r"(a[1]), "r"(a[2]), "r"(a[3]), "r"(b[0]), "r"(b[1]));
}
__device__ __forceinline__ void cpa16(uint32_t dst, const void* src) {
    asm volatile("cp.async.cg.shared.global [%0], [%1], 16;" :: "r"(dst), "l"(src));
}
#define CP_COMMIT() asm volatile("cp.async.commit_group;" ::: "memory")
#define CP_WAIT(n)  asm volatile("cp.async.wait_group " #n ";" ::: "memory")

// ---------------- Kernel 0a: build 5 shifted fp16 copies of x ----------------
// block: (seg of 2048 t) x i x b; 256 threads
__global__ void prep_x_kernel(const float* __restrict__ x) {
    __shared__ __align__(16) float xs[2052];
    const int seg = blockIdx.x, i = blockIdx.y, b = blockIdx.z;
    const int t0 = seg * 2048;
    const int tid = threadIdx.x;
    const float* xr = x + ((size_t)b * EDIM + i) * LDIM + t0;

    const float4* xv = reinterpret_cast<const float4*>(xr);
    reinterpret_cast<float4*>(xs)[2 * tid]     = xv[2 * tid];
    reinterpret_cast<float4*>(xs)[2 * tid + 1] = xv[2 * tid + 1];
    if (tid < 4)
        xs[2048 + tid] = (t0 + 2048 + tid < LDIM) ? xr[2048 + tid] : 0.0f;
    __syncthreads();

    #pragma unroll
    for (int k = 0; k < KSZ; k++) {
        uint32_t p[4];
        #pragma unroll
        for (int q = 0; q < 4; q++) {
            __half2 h2 = __floats2half2_rn(xs[tid * 8 + k + 2 * q],
                                           xs[tid * 8 + k + 2 * q + 1]);
            p[q] = *reinterpret_cast<uint32_t*>(&h2);
        }
        __half* dst = g_xh5 + (((size_t)k * BDIM + b) * EDIM + i) * LDIM + t0 + tid * 8;
        *reinterpret_cast<uint4*>(dst) = make_uint4(p[0], p[1], p[2], p[3]);
    }
}

// ---------------- Kernel 0b: weights -> g_wk5[k][e][i] fp16; zero g_s ----------------
__global__ void prep_w_kernel(const float* __restrict__ w) {
    int idx = blockIdx.x * 256 + threadIdx.x;
    if (idx < KSZ * EDIM * EDIM) {
        int k = idx / (EDIM * EDIM);
        int r = idx - k * (EDIM * EDIM);
        int e = r / EDIM, i = r - e * EDIM;
        g_wk5[idx] = __float2half_rn(w[((size_t)e * EDIM + i) * KSZ + k]);
    }
    if (idx < BDIM * LDIM) g_s[idx] = 0.0f;
}

// ---------------- Kernel 1: conv as 5 shifted fp16 GEMMs (mma.sync) ----------------
// D[t,e] = sum_k sum_i g_xh5[k][b][i][t] * g_wk5[k][e][i]
// Block 128t x 256e, 512 threads (16 warps: 4m x 4n), chunks of 16 i, cp.async double buffer.
__global__ void __launch_bounds__(512, 1)
conv_mma_kernel(const float* __restrict__ cb,
                const float* __restrict__ sw) {
    extern __shared__ char smem[];
    const uint32_t sb = smem_u32(smem);
    const int tid = threadIdx.x;
    const int wid = tid >> 5, lid = tid & 31;
    const int b  = blockIdx.z;
    const int te = blockIdx.y * NBLK;
    const int tt = blockIdx.x * MBLK;

    float acc[2][8][4];
    #pragma unroll
    for (int i = 0; i < 2; i++)
        #pragma unroll
        for (int j = 0; j < 8; j++)
            #pragma unroll
            for (int q = 0; q < 4; q++)
                acc[i][j][q] = 0.0f;

    // ---- staging lambda-ish: chunk c -> buffer c&1 via cp.async ----
    auto stage = [&](int c) {
        const int i0 = c * IBLK;
        const uint32_t bufb = sb + (c & 1) * BUF_B;
        // A: 5k x 16i x 16 t-vec16B = 1280 ops
        for (int o = tid; o < KSZ * IBLK * 16; o += 512) {
            int k = o >> 8;
            int r = o & 255;
            int i = r >> 4;
            int tc = r & 15;
            const __half* src = g_xh5 + (((size_t)k * BDIM + b) * EDIM + (i0 + i)) * LDIM
                              + tt + tc * 8;
            cpa16(bufb + k * A_TILE + i * A_STRIDE_B + tc * 16, src);
        }
        // B: 5k x 256e x 2 half-rows = 2560 ops
        for (int o = tid; o < KSZ * NBLK * 2; o += 512) {
            int k = o >> 9;
            int r = o & 511;
            int e = r >> 1;
            int h = r & 1;
            const __half* src = g_wk5 + ((size_t)k * EDIM + (te + e)) * EDIM + i0 + h * 8;
            cpa16(bufb + A_SZ + k * B_TILE + e * B_STRIDE_B + h * 16, src);
        }
    };

    const int wm = (wid & 3) * 32;     // warp m (t) offset
    const int wn = (wid >> 2) * 64;    // warp n (e) offset

    // A trans-ldmatrix lane addressing on [i][t] storage:
    // mats: a0=(tL,iL) lanes0-7; a1=(tH,iL) lanes8-15; a2=(tL,iH) lanes16-23; a3=(tH,iH) lanes24-31
    const uint32_t i_rowA = (uint32_t)((lid & 7) + ((lid & 16) ? 8 : 0));
    const uint32_t t_offA = (uint32_t)((lid & 8) ? 8 : 0);
    const uint32_t aoff   = i_rowA * A_STRIDE_B + (uint32_t)(wm + t_offA) * 2;
    // B non-trans (same as validated R14 pattern), rows e of 16 i
    const int b_q   = lid >> 3;
    const int b_row = wn + ((b_q & 2) ? 8 : 0) + (lid & 7);
    const uint32_t b_cb = (uint32_t)((b_q & 1) ? 16 : 0);

    stage(0);
    CP_COMMIT();

    for (int c = 0; c < NCHI; c++) {
        if (c + 1 < NCHI) {
            stage(c + 1);
            CP_COMMIT();
            CP_WAIT(1);
        } else {
            CP_WAIT(0);
        }
        __syncthreads();

        const uint32_t bufb  = sb + (c & 1) * BUF_B;
        const uint32_t Bbase = bufb + A_SZ;
        #pragma unroll
        for (int k = 0; k < KSZ; k++) {
            const uint32_t Ak = bufb + k * A_TILE;
            const uint32_t Bk = Bbase + k * B_TILE;
            uint32_t a0[4], a1[4];
            ldsm_x4_t(Ak + aoff, a0);
            ldsm_x4_t(Ak + aoff + 32, a1);     // +16 t
            #pragma unroll
            for (int ng = 0; ng < 4; ng++) {
                uint32_t bb[4];
                ldsm_x4(Bk + (uint32_t)(b_row + ng * 16) * B_STRIDE_B + b_cb, bb);
                mma_fp16(acc[0][2 * ng],     a0, &bb[0]);
                mma_fp16(acc[0][2 * ng + 1], a0, &bb[2]);
                mma_fp16(acc[1][2 * ng],     a1, &bb[0]);
                mma_fp16(acc[1][2 * ng + 1], a1, &bb[2]);
            }
        }
        __syncthreads();
    }

    // ---- epilogue: bias + store y + fused score projection ----
    // D fragment: c0:(t0,e0) c1:(t0,e0+1) c2:(t0+8,e0) c3:(t0+8,e0+1)
    const int r = lid & 3, qr = lid >> 2;
    #pragma unroll
    for (int mt = 0; mt < 2; mt++) {
        const int tg0 = tt + wm + mt * 16 + qr;   // and tg0 + 8
        float s0 = 0.0f, s1 = 0.0f;
        #pragma unroll
        for (int n8 = 0; n8 < 8; n8++) {
            const int e0 = te + wn + n8 * 8 + r * 2;
            const float cb0 = __ldg(&cb[e0]), cb1 = __ldg(&cb[e0 + 1]);
            const float sw0 = __ldg(&sw[e0]), sw1 = __ldg(&sw[e0 + 1]);
            float c0 = acc[mt][n8][0] + cb0;
            float c1 = acc[mt][n8][1] + cb1;
            float c2 = acc[mt][n8][2] + cb0;
            float c3 = acc[mt][n8][3] + cb1;
            float* y0 = g_y + ((size_t)b * EDIM + e0) * LDIM;
            float* y1 = y0 + LDIM;
            if (tg0 < LC)     { y0[tg0] = c0;     y1[tg0] = c1; }
            if (tg0 + 8 < LC) { y0[tg0 + 8] = c2; y1[tg0 + 8] = c3; }
            s0 += c0 * sw0 + c1 * sw1;
            s1 += c2 * sw0 + c3 * sw1;
        }
        s0 += __shfl_xor_sync(0xFFFFFFFF, s0, 1);
        s0 += __shfl_xor_sync(0xFFFFFFFF, s0, 2);
        s1 += __shfl_xor_sync(0xFFFFFFFF, s1, 1);
        s1 += __shfl_xor_sync(0xFFFFFFFF, s1, 2);
        if (r == 0) {
            if (tg0 < LC)     atomicAdd(&g_s[b * LDIM + tg0], s0);
            if (tg0 + 8 < LC) atomicAdd(&g_s[b * LDIM + tg0 + 8], s1);
        }
    }
}

// ---------------- Kernel 2: per-(b,t) softmax over widths {1,2,3} ----------------
__global__ void att_kernel() {
    const int b = blockIdx.y;
    const int t = blockIdx.x * 256 + threadIdx.x;
    const float* s = g_s + b * LDIM;

    float sc1 = (t < LC) ? s[t] : 0.0f;
    int n2 = t >> 1;
    float sc2 = (t < LC) ? 0.5f * (s[2 * n2] + s[2 * n2 + 1]) : 0.0f;
    float sc3 = 0.0f;
    int m = t / 3;
    if (t < 8190) {
        sc3 = (s[3 * m] + s[3 * m + 1] + s[3 * m + 2]) * (1.0f / 3.0f);
    }
    float mx = fmaxf(sc1, fmaxf(sc2, sc3));
    float e1 = expf(sc1 - mx), e2 = expf(sc2 - mx), e3 = expf(sc3 - mx);
    float inv = 1.0f / (e1 + e2 + e3);
    float* a = g_att + ((size_t)b * LDIM + t) * 4;
    a[0] = e1 * inv;
    a[1] = e2 * inv;
    a[2] = e3 * inv;
    a[3] = 0.0f;
}

// ---------------- Kernel 3: mix widths + downsample by 2 ----------------
__global__ void final_kernel(float* __restrict__ out) {
    const int b  = blockIdx.z;
    const int e  = blockIdx.y;
    const int td = blockIdx.x * 256 + threadIdx.x;   // 0..4095
    const float* y   = g_y   + ((size_t)b * EDIM + e) * LDIM;
    const float* att = g_att + (size_t)b * LDIM * 4;

    float z[2];
    #pragma unroll
    for (int h = 0; h < 2; h++) {
        int t = 2 * td + h;
        float4 a4 = *reinterpret_cast<const float4*>(att + (size_t)t * 4);

        float v1 = (t < LC) ? y[t] : 0.0f;

        int n2 = t >> 1;
        float v2 = (t < LC) ? 0.5f * (y[2 * n2] + y[2 * n2 + 1]) : 0.0f;

        float v3 = 0.0f;
        if (t < 8190) {
            int i0 = 3 * (t / 3);
            float s0 = y[i0];
            float s1 = (i0 + 1 < LC) ? y[i0 + 1] : 0.0f;
            float s2 = (i0 + 2 < LC) ? y[i0 + 2] : 0.0f;
            v3 = (s0 + s1 + s2) * (1.0f / 3.0f);
        }
        z[h] = v1 * a4.x + v2 * a4.y + v3 * a4.z;
    }
    out[((size_t)b * EDIM + e) * TD + td] = 0.5f * (z[0] + z[1]);
}

// ---------------- launch ----------------
extern "C" void kernel_launch(void* const* d_in, const int* in_sizes, int n_in,
                              void* d_out, int out_size) {
    (void)in_sizes; (void)n_in; (void)out_size;
    const float* x  = (const float*)d_in[0];   // [8,512,8192]
    const float* cw = (const float*)d_in[1];   // [512,512,5]
    const float* cb = (const float*)d_in[2];   // [512]
    const float* sw = (const float*)d_in[3];   // [512]
    float* out = (float*)d_out;                // [8,512,4096]

    cudaFuncSetAttribute(conv_mma_kernel,
                         cudaFuncAttributeMaxDynamicSharedMemorySize, SMEM_TOTAL);

    prep_x_kernel<<<dim3(LDIM / 2048, EDIM, BDIM), 256>>>(x);
    prep_w_kernel<<<(KSZ * EDIM * EDIM + 255) / 256, 256>>>(cw);
    conv_mma_kernel<<<dim3(LDIM / MBLK, EDIM / NBLK, BDIM), 512, SMEM_TOTAL>>>(cb, sw);
    att_kernel<<<dim3(LDIM / 256, BDIM), 256>>>();
    final_kernel<<<dim3(TD / 256, EDIM, BDIM), 256>>>(out);
}